// round 5
// baseline (speedup 1.0000x reference)
#include <cuda_runtime.h>
#include <cuda_bf16.h>

// VariableSelectionNetwork: B=32, S=512, F=32, H=64
//   A[f][g] = sum_h W_feat[f,h]*W_gate[f*H+h, g];  c[g] = b_gate[g] + sum b_feat.W_gate
//   gates = softmax(x @ A + c);  out = [g*x, g] @ [W_feat; b_feat]
// Kernel 1 (prep): partial A/c over 4 h-quarters, 128 blocks.
// Kernel 2 (main): fused gates + 64x64 GEMM per 64-row tile, full-k per thread.

#define F_DIM 32
#define H_DIM 64
#define ROWS  16384
#define MB_ROWS 64
#define MAIN_GRID (ROWS / MB_ROWS)   // 256

__device__ float g_Apart[4 * 1024];
__device__ float g_Cpart[4 * 1024];

// ---------------- f32x2 helpers ----------------
__device__ __forceinline__ unsigned long long pk2(float a, float b) {
    unsigned long long r;
    asm("mov.b64 %0, {%1, %2};" : "=l"(r) : "f"(a), "f"(b));
    return r;
}
__device__ __forceinline__ void ffma2(unsigned long long& d,
                                      unsigned long long a,
                                      unsigned long long b) {
    asm("fma.rn.f32x2 %0, %1, %2, %3;" : "=l"(d) : "l"(a), "l"(b), "l"(d));
}
__device__ __forceinline__ float2 unpk2(unsigned long long v) {
    float2 r;
    asm("mov.b64 {%0, %1}, %2;" : "=f"(r.x), "=f"(r.y) : "l"(v));
    return r;
}

// ---------------------------------------------------------------------------
// Prep: 128 blocks (f = bid>>2, h-quarter q = bid&3), 128 threads.
// ---------------------------------------------------------------------------
__global__ void __launch_bounds__(128) vsn_prep_kernel(
    const float* __restrict__ W_feat,
    const float* __restrict__ b_feat,
    const float* __restrict__ W_gate)
{
    const int f  = blockIdx.x >> 2;
    const int q  = blockIdx.x & 3;
    const int g  = threadIdx.x & 31;
    const int hh = threadIdx.x >> 5;

    float a = 0.f, c = 0.f;
#pragma unroll
    for (int kk = 0; kk < 4; kk++) {
        const int h = q * 16 + hh * 4 + kk;
        const float wg = W_gate[(f * H_DIM + h) * F_DIM + g];
        a = fmaf(W_feat[f * H_DIM + h], wg, a);
        c = fmaf(b_feat[f * H_DIM + h], wg, c);
    }

    __shared__ float rA[4][32];
    __shared__ float rC[4][32];
    rA[hh][g] = a;
    rC[hh][g] = c;
    __syncthreads();

    if (threadIdx.x < 32) {
        float as = 0.f, cs = 0.f;
#pragma unroll
        for (int r = 0; r < 4; r++) { as += rA[r][threadIdx.x]; cs += rC[r][threadIdx.x]; }
        g_Apart[q * 1024 + f * F_DIM + threadIdx.x] = as;
        g_Cpart[q * 1024 + f * F_DIM + threadIdx.x] = cs;
    }
}

// ---------------------------------------------------------------------------
// Main: 256 blocks x 256 threads, 64 rows per block.
//   sWB [64][64] 16 KB, sX [64][64] 16 KB (k-major), sA 4 KB.
// Phase 1: 4 threads/row compute gates, write X'.
// Phase 2: thread tile 4 rows x 4 cols, full k=64, f32x2 accumulate.
// ---------------------------------------------------------------------------
__global__ void __launch_bounds__(256) vsn_main_kernel(
    const float* __restrict__ features,
    const float* __restrict__ b_gate,
    const float* __restrict__ W_feat,
    const float* __restrict__ b_feat,
    float* __restrict__ out)
{
    __shared__ __align__(16) float sWB[2 * F_DIM * H_DIM];  // [k][h] 16 KB
    __shared__ __align__(16) float sX [2 * F_DIM * MB_ROWS];// [k][row] 16 KB
    __shared__ __align__(16) float sA [F_DIM * F_DIM];      // 4 KB
    __shared__ __align__(16) float sc [F_DIM];
    __shared__ float sCred[8][32];

    const int tid = threadIdx.x;

    // ---- Stage params ----
#pragma unroll
    for (int i = tid; i < 1024; i += 256) {      // sWB as 1024 float4
        const int k   = i >> 4;
        const int seg = i & 15;
        const float* src = (k < F_DIM ? W_feat + k * H_DIM
                                      : b_feat + (k - F_DIM) * H_DIM) + seg * 4;
        *(float4*)(sWB + k * H_DIM + seg * 4) = *(const float4*)src;
    }
#pragma unroll
    for (int j = 0; j < 4; j++) {                // fold A partials
        const int i = tid + j * 256;
        sA[i] = g_Apart[i] + g_Apart[1024 + i] + g_Apart[2048 + i] + g_Apart[3072 + i];
    }
    {                                            // fold c partials
        const int g  = tid & 31;
        const int ch = tid >> 5;
        float s = 0.f;
#pragma unroll
        for (int e = 0; e < 16; e++) {
            const int ee = ch * 16 + e;
            s += g_Cpart[(ee >> 5) * 1024 + (ee & 31) * F_DIM + g];
        }
        sCred[ch][g] = s;
    }
    __syncthreads();
    if (tid < 32) {
        float cv = b_gate[tid];
#pragma unroll
        for (int r = 0; r < 8; r++) cv += sCred[r][tid];
        sc[tid] = cv;
    }
    __syncthreads();

    // ---- Phase 1: gates (4 threads per row / quad) ----
    const int rowL = tid >> 2;                   // 0..63
    const int q    = tid & 3;
    const int lane = tid & 31;
    const int row  = blockIdx.x * MB_ROWS + rowL;

    float x[F_DIM];
    {
        const float4* xr = (const float4*)(features + row * F_DIM);
#pragma unroll
        for (int i = 0; i < 8; i++) {
            float4 v = xr[i];
            x[4*i+0] = v.x; x[4*i+1] = v.y; x[4*i+2] = v.z; x[4*i+3] = v.w;
        }
    }

    // logits l[8] = x @ A[:, q*8 .. q*8+8) + c   (as 4 f32x2)
    unsigned long long l2[4];
    {
        const ulonglong2* cp = (const ulonglong2*)(sc + q * 8);
        ulonglong2 ca = cp[0], cb = cp[1];
        l2[0] = ca.x; l2[1] = ca.y; l2[2] = cb.x; l2[3] = cb.y;
    }
#pragma unroll
    for (int f = 0; f < F_DIM; f++) {
        const unsigned long long xp = pk2(x[f], x[f]);
        const ulonglong2* ap = (const ulonglong2*)(sA + f * F_DIM + q * 8);
        ulonglong2 a0 = ap[0], a1 = ap[1];
        ffma2(l2[0], xp, a0.x); ffma2(l2[1], xp, a0.y);
        ffma2(l2[2], xp, a1.x); ffma2(l2[3], xp, a1.y);
    }
    float le[8];
#pragma unroll
    for (int i = 0; i < 4; i++) {
        float2 v = unpk2(l2[i]);
        le[2*i] = v.x; le[2*i+1] = v.y;
    }

    // softmax across quad
    float m = le[0];
#pragma unroll
    for (int j = 1; j < 8; j++) m = fmaxf(m, le[j]);
    m = fmaxf(m, __shfl_xor_sync(0xffffffffu, m, 1));
    m = fmaxf(m, __shfl_xor_sync(0xffffffffu, m, 2));
    float s = 0.f;
#pragma unroll
    for (int j = 0; j < 8; j++) { le[j] = __expf(le[j] - m); s += le[j]; }
    s += __shfl_xor_sync(0xffffffffu, s, 1);
    s += __shfl_xor_sync(0xffffffffu, s, 2);
    const float inv = 1.f / s;

    // write X' (k-major): sX[f][rowL] = g*x[f], sX[32+f][rowL] = g
    const int fb = q * 8;
#pragma unroll
    for (int j = 0; j < 8; j++) {
        const float gj = le[j] * inv;
        sX[(fb + j) * MB_ROWS + rowL]         = gj * x[fb + j];
        sX[(F_DIM + fb + j) * MB_ROWS + rowL] = gj;
    }
    __syncthreads();

    // ---- Phase 2: out = X' @ W', thread tile 4 rows x 4 cols, k=64 ----
    const int rg = tid >> 4;        // 0..15 -> rows rg*4
    const int cg = tid & 15;        // 0..15 -> cols cg*4
    const int r0 = rg * 4;
    const int c0 = cg * 4;

    unsigned long long acc[4][2];
#pragma unroll
    for (int r = 0; r < 4; r++) { acc[r][0] = 0ull; acc[r][1] = 0ull; }

#pragma unroll 16
    for (int k = 0; k < 2 * F_DIM; k++) {
        const float4 xv = *(const float4*)(sX + k * MB_ROWS + r0);
        const ulonglong2 wv = *(const ulonglong2*)(sWB + k * H_DIM + c0);
        const unsigned long long x0 = pk2(xv.x, xv.x);
        const unsigned long long x1 = pk2(xv.y, xv.y);
        const unsigned long long x2 = pk2(xv.z, xv.z);
        const unsigned long long x3 = pk2(xv.w, xv.w);
        ffma2(acc[0][0], x0, wv.x); ffma2(acc[0][1], x0, wv.y);
        ffma2(acc[1][0], x1, wv.x); ffma2(acc[1][1], x1, wv.y);
        ffma2(acc[2][0], x2, wv.x); ffma2(acc[2][1], x2, wv.y);
        ffma2(acc[3][0], x3, wv.x); ffma2(acc[3][1], x3, wv.y);
    }

    // store 4 rows x 4 cols
    const int rowbase = blockIdx.x * MB_ROWS + r0;
#pragma unroll
    for (int r = 0; r < 4; r++) {
        const float2 lo = unpk2(acc[r][0]);
        const float2 hi = unpk2(acc[r][1]);
        *(float4*)(out + (rowbase + r) * H_DIM + c0) =
            make_float4(lo.x, lo.y, hi.x, hi.y);
    }
}

extern "C" void kernel_launch(void* const* d_in, const int* in_sizes, int n_in,
                              void* d_out, int out_size)
{
    const float* features = (const float*)d_in[0];   // [32,512,32]
    const float* W_feat   = (const float*)d_in[1];   // [32,64]
    const float* b_feat   = (const float*)d_in[2];   // [32,64]
    const float* W_gate   = (const float*)d_in[3];   // [2048,32]
    const float* b_gate   = (const float*)d_in[4];   // [32]
    float* out = (float*)d_out;                      // [32,512,64]

    vsn_prep_kernel<<<128, 128>>>(W_feat, b_feat, W_gate);
    vsn_main_kernel<<<MAIN_GRID, 256>>>(features, b_gate, W_feat, b_feat, out);
}

// round 7
// speedup vs baseline: 1.1184x; 1.1184x over previous
#include <cuda_runtime.h>
#include <cuda_bf16.h>

// VariableSelectionNetwork: B=32, S=512, F=32, H=64
//   A[f][g] = sum_h W_feat[f,h]*W_gate[f*H+h, g];  c[g] = b_gate[g] + sum b_feat.W_gate
//   gates = softmax(x @ A + c);  out = [g*x, g] @ [W_feat; b_feat]
// Prep: partial A/c over 4 h-quarters, 128 blocks.
// Main: 256 blocks x 128 threads, 64 rows/block; fused gates + GEMM,
//       phase-2 tile 4 rows x 8 cols, full k=64, f32x2 FMAs.

#define F_DIM 32
#define H_DIM 64
#define ROWS  16384
#define MB_ROWS 64
#define MAIN_GRID (ROWS / MB_ROWS)   // 256

__device__ float g_Apart[4 * 1024];
__device__ float g_Cpart[4 * 1024];

// ---------------- f32x2 helpers ----------------
__device__ __forceinline__ unsigned long long pk2(float a, float b) {
    unsigned long long r;
    asm("mov.b64 %0, {%1, %2};" : "=l"(r) : "f"(a), "f"(b));
    return r;
}
__device__ __forceinline__ void ffma2(unsigned long long& d,
                                      unsigned long long a,
                                      unsigned long long b) {
    asm("fma.rn.f32x2 %0, %1, %2, %3;" : "=l"(d) : "l"(a), "l"(b), "l"(d));
}
__device__ __forceinline__ float2 unpk2(unsigned long long v) {
    float2 r;
    asm("mov.b64 {%0, %1}, %2;" : "=f"(r.x), "=f"(r.y) : "l"(v));
    return r;
}

// ---------------------------------------------------------------------------
// Prep: 128 blocks (f = bid>>2, h-quarter q = bid&3), 128 threads.
// ---------------------------------------------------------------------------
__global__ void __launch_bounds__(128) vsn_prep_kernel(
    const float* __restrict__ W_feat,
    const float* __restrict__ b_feat,
    const float* __restrict__ W_gate)
{
    const int f  = blockIdx.x >> 2;
    const int q  = blockIdx.x & 3;
    const int g  = threadIdx.x & 31;
    const int hh = threadIdx.x >> 5;

    float a = 0.f, c = 0.f;
#pragma unroll
    for (int kk = 0; kk < 4; kk++) {
        const int h = q * 16 + hh * 4 + kk;
        const float wg = W_gate[(f * H_DIM + h) * F_DIM + g];
        a = fmaf(W_feat[f * H_DIM + h], wg, a);
        c = fmaf(b_feat[f * H_DIM + h], wg, c);
    }

    __shared__ float rA[4][32];
    __shared__ float rC[4][32];
    rA[hh][g] = a;
    rC[hh][g] = c;
    __syncthreads();

    if (threadIdx.x < 32) {
        float as = 0.f, cs = 0.f;
#pragma unroll
        for (int r = 0; r < 4; r++) { as += rA[r][threadIdx.x]; cs += rC[r][threadIdx.x]; }
        g_Apart[q * 1024 + f * F_DIM + threadIdx.x] = as;
        g_Cpart[q * 1024 + f * F_DIM + threadIdx.x] = cs;
    }
}

// ---------------------------------------------------------------------------
// Main kernel.
//   sWB [64][64] 16 KB  (combined [W_feat; b_feat], k-major)
//   sX  [64][64] 16 KB  (X' k-major: sX[k][row])
//   sA  [32][32]  4 KB
// Phase 1: 2 threads/row (16 logits each) -> gates -> X' to smem.
// Phase 2: tile 4 rows x 8 cols per thread, full k=64.
// ---------------------------------------------------------------------------
__global__ void __launch_bounds__(128, 4) vsn_main_kernel(
    const float* __restrict__ features,
    const float* __restrict__ b_gate,
    const float* __restrict__ W_feat,
    const float* __restrict__ b_feat,
    float* __restrict__ out)
{
    __shared__ __align__(16) float sWB[2 * F_DIM * H_DIM];   // 4096
    __shared__ __align__(16) float sX [2 * F_DIM * MB_ROWS]; // 4096
    __shared__ __align__(16) float sA [F_DIM * F_DIM];       // 1024
    __shared__ __align__(16) float sc [F_DIM];
    __shared__ float sCred[4][32];

    const int tid = threadIdx.x;

    // ---- Stage params ----
#pragma unroll
    for (int i = tid; i < 1024; i += 128) {      // sWB as 1024 float4
        const int k   = i >> 4;
        const int seg = i & 15;
        const float* src = (k < F_DIM ? W_feat + k * H_DIM
                                      : b_feat + (k - F_DIM) * H_DIM) + seg * 4;
        *(float4*)(sWB + k * H_DIM + seg * 4) = *(const float4*)src;
    }
#pragma unroll
    for (int j = 0; j < 8; j++) {                // fold A partials
        const int i = tid + j * 128;
        sA[i] = g_Apart[i] + g_Apart[1024 + i] + g_Apart[2048 + i] + g_Apart[3072 + i];
    }
    {                                            // fold c partials
        const int g  = tid & 31;
        const int ch = tid >> 5;                 // 0..3
        float s = 0.f;
#pragma unroll
        for (int e = 0; e < 32; e++) {
            const int ee = ch * 32 + e;          // (q,f) flat 0..127
            s += g_Cpart[(ee >> 5) * 1024 + (ee & 31) * F_DIM + g];
        }
        sCred[ch][g] = s;
    }
    __syncthreads();
    if (tid < 32) {
        float cv = b_gate[tid];
#pragma unroll
        for (int r = 0; r < 4; r++) cv += sCred[r][tid];
        sc[tid] = cv;
    }
    __syncthreads();

    // ---- Phase 1: gates (2 threads per row, 16 logits each) ----
    const int rowL  = tid >> 1;                  // 0..63
    const int half  = tid & 1;
    const int fbase = half * 16;
    const int row   = blockIdx.x * MB_ROWS + rowL;

    float x[F_DIM];
    {
        const float4* xr = (const float4*)(features + row * F_DIM);
#pragma unroll
        for (int i = 0; i < 8; i++) {
            float4 v = xr[i];
            x[4*i+0] = v.x; x[4*i+1] = v.y; x[4*i+2] = v.z; x[4*i+3] = v.w;
        }
    }

    unsigned long long l2[8];
    {
        const ulonglong2* cp = (const ulonglong2*)(sc + fbase);
        ulonglong2 c0 = cp[0], c1 = cp[1], c2 = cp[2], c3 = cp[3];
        l2[0]=c0.x; l2[1]=c0.y; l2[2]=c1.x; l2[3]=c1.y;
        l2[4]=c2.x; l2[5]=c2.y; l2[6]=c3.x; l2[7]=c3.y;
    }
#pragma unroll
    for (int f = 0; f < F_DIM; f++) {
        const unsigned long long xp = pk2(x[f], x[f]);
        const ulonglong2* ap = (const ulonglong2*)(sA + f * F_DIM + fbase);
        ulonglong2 a0 = ap[0], a1 = ap[1], a2 = ap[2], a3 = ap[3];
        ffma2(l2[0], xp, a0.x); ffma2(l2[1], xp, a0.y);
        ffma2(l2[2], xp, a1.x); ffma2(l2[3], xp, a1.y);
        ffma2(l2[4], xp, a2.x); ffma2(l2[5], xp, a2.y);
        ffma2(l2[6], xp, a3.x); ffma2(l2[7], xp, a3.y);
    }
    float le[16];
#pragma unroll
    for (int i = 0; i < 8; i++) {
        float2 v = unpk2(l2[i]);
        le[2*i] = v.x; le[2*i+1] = v.y;
    }

    // Softmax: 16 local + partner (lane^1)
    float m = le[0];
#pragma unroll
    for (int j = 1; j < 16; j++) m = fmaxf(m, le[j]);
    m = fmaxf(m, __shfl_xor_sync(0xffffffffu, m, 1));
    float s = 0.f;
#pragma unroll
    for (int j = 0; j < 16; j++) { le[j] = __expf(le[j] - m); s += le[j]; }
    s += __shfl_xor_sync(0xffffffffu, s, 1);
    const float inv = 1.f / s;

    // Write X' (k-major): sX[f][rowL] = g*x[f]; sX[32+f][rowL] = g
#pragma unroll
    for (int j = 0; j < 16; j++) {
        const float gj = le[j] * inv;
        sX[(fbase + j) * MB_ROWS + rowL]         = gj * x[fbase + j];
        sX[(F_DIM + fbase + j) * MB_ROWS + rowL] = gj;
    }
    __syncthreads();

    // ---- Phase 2: out = X' @ W', tile 4 rows x 8 cols, full k=64 ----
    const int rg = tid >> 3;        // 0..15 -> rows rg*4
    const int cg = tid & 7;         // 0..7  -> cols cg*8
    const int r0 = rg * 4;
    const int c0 = cg * 8;

    unsigned long long acc[4][4];
#pragma unroll
    for (int r = 0; r < 4; r++)
#pragma unroll
        for (int p = 0; p < 4; p++) acc[r][p] = 0ull;

#pragma unroll 16
    for (int k = 0; k < 2 * F_DIM; k++) {
        const float4 xv = *(const float4*)(sX + k * MB_ROWS + r0);
        const ulonglong2* wp = (const ulonglong2*)(sWB + k * H_DIM + c0);
        const ulonglong2 w0 = wp[0], w1 = wp[1];

        const unsigned long long x0 = pk2(xv.x, xv.x);
        const unsigned long long x1 = pk2(xv.y, xv.y);
        const unsigned long long x2 = pk2(xv.z, xv.z);
        const unsigned long long x3 = pk2(xv.w, xv.w);

        ffma2(acc[0][0], x0, w0.x); ffma2(acc[0][1], x0, w0.y);
        ffma2(acc[0][2], x0, w1.x); ffma2(acc[0][3], x0, w1.y);
        ffma2(acc[1][0], x1, w0.x); ffma2(acc[1][1], x1, w0.y);
        ffma2(acc[1][2], x1, w1.x); ffma2(acc[1][3], x1, w1.y);
        ffma2(acc[2][0], x2, w0.x); ffma2(acc[2][1], x2, w0.y);
        ffma2(acc[2][2], x2, w1.x); ffma2(acc[2][3], x2, w1.y);
        ffma2(acc[3][0], x3, w0.x); ffma2(acc[3][1], x3, w0.y);
        ffma2(acc[3][2], x3, w1.x); ffma2(acc[3][3], x3, w1.y);
    }

    // Store 4 rows x 8 cols
    const int rowbase = blockIdx.x * MB_ROWS + r0;
#pragma unroll
    for (int r = 0; r < 4; r++) {
        const float2 v0 = unpk2(acc[r][0]);
        const float2 v1 = unpk2(acc[r][1]);
        const float2 v2 = unpk2(acc[r][2]);
        const float2 v3 = unpk2(acc[r][3]);
        float* dst = out + (rowbase + r) * H_DIM + c0;
        *(float4*)(dst)     = make_float4(v0.x, v0.y, v1.x, v1.y);
        *(float4*)(dst + 4) = make_float4(v2.x, v2.y, v3.x, v3.y);
    }
}

extern "C" void kernel_launch(void* const* d_in, const int* in_sizes, int n_in,
                              void* d_out, int out_size)
{
    const float* features = (const float*)d_in[0];   // [32,512,32]
    const float* W_feat   = (const float*)d_in[1];   // [32,64]
    const float* b_feat   = (const float*)d_in[2];   // [32,64]
    const float* W_gate   = (const float*)d_in[3];   // [2048,32]
    const float* b_gate   = (const float*)d_in[4];   // [32]
    float* out = (float*)d_out;                      // [32,512,64]

    vsn_prep_kernel<<<128, 128>>>(W_feat, b_feat, W_gate);
    vsn_main_kernel<<<MAIN_GRID, 128>>>(features, b_gate, W_feat, b_feat, out);
}